// round 14
// baseline (speedup 1.0000x reference)
#include <cuda_runtime.h>
#include <cuda_bf16.h>
#include <cuda_fp16.h>
#include <math.h>

#define MAXN 50000
#define MAXE 800000
#define IN_DIM 128
#define TD 128
#define HT 256
#define NH 4
#define NEG_SLOPE 0.2f

// ---------------- device scratch ----------------
__device__ int   g_deg[MAXN];
__device__ int   g_row[MAXN + 1];
__device__ int   g_cur[MAXN];
__device__ int   g_part[64];
__device__ int   g_src_s[MAXE];
__device__ float g_t_s[MAXE];
__device__ float g_htime[(size_t)MAXN * HT];
__device__ unsigned g_feat16[(size_t)MAXN * 64];   // feat as packed half2
__device__ float g_el[MAXN * NH];
__device__ float g_er[MAXN * NH];
__device__ unsigned g_Whi[256 * 128];   // packed bf16x2 pairs along k
__device__ unsigned g_Wlo[256 * 128];

// ---------------- bf16 split helpers ----------------
__device__ __forceinline__ unsigned pk(__nv_bfloat16 a, __nv_bfloat16 b) {
    __nv_bfloat162 t = __halves2bfloat162(a, b);
    return *(unsigned*)&t;
}
__device__ __forceinline__ void bsplit2(float x0, float x1, unsigned &h, unsigned &l) {
    __nv_bfloat16 h0 = __float2bfloat16(x0);
    __nv_bfloat16 h1 = __float2bfloat16(x1);
    __nv_bfloat16 l0 = __float2bfloat16(x0 - __bfloat162float(h0));
    __nv_bfloat16 l1 = __float2bfloat16(x1 - __bfloat162float(h1));
    h = pk(h0, h1);
    l = pk(l0, l1);
}

// ---------------- W precompute (bf16 hi/lo pairs) + deg zero (fused) -------------
__global__ void k_prep(const float* __restrict__ Wfc, const float* __restrict__ Wres, int N) {
    int b = blockIdx.x;
    if (b < 128) {
        int idx = b * 256 + threadIdx.x;      // pair index 0..32767
        int row = idx >> 7, kp = idx & 127;
        const float* Wsrc = (row < 128) ? (Wfc + (size_t)row * 256)
                                        : (Wres + (size_t)(row - 128) * 256);
        float x0 = Wsrc[2 * kp], x1 = Wsrc[2 * kp + 1];
        unsigned h, l;
        bsplit2(x0, x1, h, l);
        g_Whi[idx] = h;
        g_Wlo[idx] = l;
    } else {
        int i = (b - 128) * 256 + threadIdx.x;
        if (i < N) g_deg[i] = 0;
    }
}

// ---------------- CSR build ----------------
__global__ void k_count(const int* __restrict__ dst, int E) {
    int e = blockIdx.x * blockDim.x + threadIdx.x;
    if (e < E) atomicAdd(&g_deg[dst[e]], 1);
}

__global__ void k_scan1(int N) {
    __shared__ int s[1024];
    int t = threadIdx.x;
    int i = blockIdx.x * 1024 + t;
    int v = (i < N) ? g_deg[i] : 0;
    s[t] = v;
    __syncthreads();
    for (int off = 1; off < 1024; off <<= 1) {
        int x = (t >= off) ? s[t - off] : 0;
        __syncthreads();
        s[t] += x;
        __syncthreads();
    }
    if (i < N) g_row[i] = s[t];
    if (t == 1023) g_part[blockIdx.x] = s[1023];
}

// scan3 with warp-parallel partial-prefix (NB <= 64)
__global__ void k_scan3(int N, int E) {
    __shared__ int sbase;
    int t = threadIdx.x, b = blockIdx.x;
    if (t < 32) {
        int v = (t < b ? g_part[t] : 0) + (t + 32 < b ? g_part[t + 32] : 0);
#pragma unroll
        for (int off = 16; off >= 1; off >>= 1)
            v += __shfl_xor_sync(0xffffffffu, v, off);
        if (t == 0) sbase = v;
    }
    __syncthreads();
    int i = blockIdx.x * blockDim.x + t;
    if (i < N) {
        int ex = g_row[i] - g_deg[i] + sbase;
        g_row[i] = ex;
        g_cur[i] = ex;
    }
    if (i == 0) g_row[N] = E;
}

__global__ void k_fill(const int* __restrict__ src, const int* __restrict__ dst,
                       const float* __restrict__ tt, int E) {
    int e = blockIdx.x * blockDim.x + threadIdx.x;
    if (e < E) {
        int slot = atomicAdd(&g_cur[dst[e]], 1);
        g_src_s[slot] = src[e];
        g_t_s[slot]   = tt[e];
    }
}

// ---------------- mailbox mean (warp per dst node, index prefetch) ----------------
__global__ void k_agg(const float* __restrict__ h,
                      const float* __restrict__ w_t,
                      const float* __restrict__ b_t, int N) {
    __shared__ float sw[TD], sb[TD];
    int t = threadIdx.x;
    for (int i = t; i < TD; i += blockDim.x) { sw[i] = w_t[i]; sb[i] = b_t[i]; }
    __syncthreads();
    int warp = (blockIdx.x * blockDim.x + t) >> 5;
    int lane = t & 31;
    if (warp >= N) return;
    int rs = g_row[warp], re = g_row[warp + 1];
    float w0 = sw[lane*4], w1 = sw[lane*4+1], w2 = sw[lane*4+2], w3 = sw[lane*4+3];
    float b0 = sb[lane*4], b1 = sb[lane*4+1], b2 = sb[lane*4+2], b3 = sb[lane*4+3];
    float4 ah = make_float4(0.f,0.f,0.f,0.f);
    float4 at = make_float4(0.f,0.f,0.f,0.f);
    const float4* h4 = (const float4*)h;
    int s_nxt = 0; float t_nxt = 0.f;
    if (rs < re) { s_nxt = g_src_s[rs]; t_nxt = g_t_s[rs]; }
    for (int j = rs; j < re; j++) {
        int s = s_nxt; float tv = t_nxt;
        if (j + 1 < re) { s_nxt = g_src_s[j + 1]; t_nxt = g_t_s[j + 1]; }
        float4 hv = h4[(size_t)s * 32 + lane];
        ah.x += hv.x; ah.y += hv.y; ah.z += hv.z; ah.w += hv.w;
        at.x += __cosf(fmaf(tv, w0, b0));
        at.y += __cosf(fmaf(tv, w1, b1));
        at.z += __cosf(fmaf(tv, w2, b2));
        at.w += __cosf(fmaf(tv, w3, b3));
    }
    float inv = 1.0f / fmaxf((float)(re - rs), 1.0f);
    float4 o1 = make_float4(ah.x*inv, ah.y*inv, ah.z*inv, ah.w*inv);
    float4 o2 = make_float4(at.x*inv, at.y*inv, at.z*inv, at.w*inv);
    float4* ht4 = (float4*)g_htime;
    ht4[(size_t)warp * 64 + lane]      = o1;
    ht4[(size_t)warp * 64 + 32 + lane] = o2;
}

// ---------------- tensor-core GEMM (bf16x3, m16n8k16, double-buffered) ------------
#define BM 128
#define BN 128
#define BK 16
#define PADW 12
#define STAGEW (128 * PADW)
#define SMEM_GEMM_BYTES (4 * 2 * STAGEW * 4)   // 48 KB

#define MMA_BF16(C, A, B)                                                      \
  asm volatile("mma.sync.aligned.m16n8k16.row.col.f32.bf16.bf16.f32 "          \
    "{%0,%1,%2,%3}, {%4,%5,%6,%7}, {%8,%9}, {%0,%1,%2,%3};\n"                  \
    : "+f"(C[0]), "+f"(C[1]), "+f"(C[2]), "+f"(C[3])                           \
    : "r"(A[0]), "r"(A[1]), "r"(A[2]), "r"(A[3]), "r"(B[0]), "r"(B[1]))

__global__ __launch_bounds__(512)
void k_gemm(float* __restrict__ res_out,
            const float* __restrict__ attn_l, const float* __restrict__ attn_r, int N) {
    extern __shared__ unsigned smem_u[];
    unsigned* As_hi = smem_u;
    unsigned* As_lo = As_hi + 2 * STAGEW;
    unsigned* Bs_hi = As_lo + 2 * STAGEW;
    unsigned* Bs_lo = Bs_hi + 2 * STAGEW;
#define AH(st,m,w) As_hi[(st)*STAGEW + (m)*PADW + (w)]
#define AL(st,m,w) As_lo[(st)*STAGEW + (m)*PADW + (w)]
#define BH(st,n,w) Bs_hi[(st)*STAGEW + (n)*PADW + (w)]
#define BL(st,n,w) Bs_lo[(st)*STAGEW + (n)*PADW + (w)]

    int n0 = blockIdx.x * BM;
    int o0 = blockIdx.y * BN;
    int tid = threadIdx.x;
    int wid = tid >> 5, lane = tid & 31;
    int mw = wid >> 2, nw = wid & 3;
    int mbase = mw * 32, nbase = nw * 32;
    int g = lane >> 2, t4 = lane & 3;

    int a_r = tid >> 2, q = tid & 3;

    float4 pa = make_float4(0.f, 0.f, 0.f, 0.f);
    if (n0 + a_r < N)
        pa = *(const float4*)&g_htime[(size_t)(n0 + a_r) * HT + 4 * q];
    uint2 pbh = *(const uint2*)&g_Whi[(o0 + a_r) * 128 + 2 * q];
    uint2 pbl = *(const uint2*)&g_Wlo[(o0 + a_r) * 128 + 2 * q];

    {
        unsigned h0, l0, h1, l1;
        bsplit2(pa.x, pa.y, h0, l0);
        bsplit2(pa.z, pa.w, h1, l1);
        AH(0,a_r,2*q) = h0;  AH(0,a_r,2*q+1) = h1;
        AL(0,a_r,2*q) = l0;  AL(0,a_r,2*q+1) = l1;
        BH(0,a_r,2*q) = pbh.x; BH(0,a_r,2*q+1) = pbh.y;
        BL(0,a_r,2*q) = pbl.x; BL(0,a_r,2*q+1) = pbl.y;
    }
    __syncthreads();

    float acc[2][4][4];
#pragma unroll
    for (int i = 0; i < 2; i++)
#pragma unroll
        for (int j = 0; j < 4; j++)
#pragma unroll
            for (int k = 0; k < 4; k++) acc[i][j][k] = 0.f;

    int st = 0;
    for (int k0 = 0; k0 < HT; k0 += BK, st ^= 1) {
        int nk = k0 + BK;
        if (nk < HT) {
            pa = make_float4(0.f, 0.f, 0.f, 0.f);
            if (n0 + a_r < N)
                pa = *(const float4*)&g_htime[(size_t)(n0 + a_r) * HT + nk + 4 * q];
            pbh = *(const uint2*)&g_Whi[(o0 + a_r) * 128 + (nk >> 1) + 2 * q];
            pbl = *(const uint2*)&g_Wlo[(o0 + a_r) * 128 + (nk >> 1) + 2 * q];
        }
        unsigned ah[2][4], al[2][4], bh[4][2], bl[4][2];
#pragma unroll
        for (int mt = 0; mt < 2; mt++) {
            int ar = mbase + mt * 16 + g;
            ah[mt][0] = AH(st,ar,t4);    ah[mt][1] = AH(st,ar+8,t4);
            ah[mt][2] = AH(st,ar,t4+4);  ah[mt][3] = AH(st,ar+8,t4+4);
            al[mt][0] = AL(st,ar,t4);    al[mt][1] = AL(st,ar+8,t4);
            al[mt][2] = AL(st,ar,t4+4);  al[mt][3] = AL(st,ar+8,t4+4);
        }
#pragma unroll
        for (int nt = 0; nt < 4; nt++) {
            int bc = nbase + nt * 8 + g;
            bh[nt][0] = BH(st,bc,t4);    bh[nt][1] = BH(st,bc,t4+4);
            bl[nt][0] = BL(st,bc,t4);    bl[nt][1] = BL(st,bc,t4+4);
        }
#pragma unroll
        for (int mt = 0; mt < 2; mt++)
#pragma unroll
            for (int nt = 0; nt < 4; nt++) {
                MMA_BF16(acc[mt][nt], ah[mt], bh[nt]);
                MMA_BF16(acc[mt][nt], al[mt], bh[nt]);
                MMA_BF16(acc[mt][nt], ah[mt], bl[nt]);
            }
        if (nk < HT) {
            int ns = st ^ 1;
            unsigned h0, l0, h1, l1;
            bsplit2(pa.x, pa.y, h0, l0);
            bsplit2(pa.z, pa.w, h1, l1);
            AH(ns,a_r,2*q) = h0;  AH(ns,a_r,2*q+1) = h1;
            AL(ns,a_r,2*q) = l0;  AL(ns,a_r,2*q+1) = l1;
            BH(ns,a_r,2*q) = pbh.x; BH(ns,a_r,2*q+1) = pbh.y;
            BL(ns,a_r,2*q) = pbl.x; BL(ns,a_r,2*q+1) = pbl.y;
        }
        __syncthreads();
    }

    // ---------- store C: feat -> packed fp16, res -> fp32 ----------
#pragma unroll
    for (int mt = 0; mt < 2; mt++)
#pragma unroll
        for (int nt = 0; nt < 4; nt++) {
            int row = n0 + mbase + mt * 16 + g;
            int col = nbase + nt * 8 + t4 * 2;
            if (o0 == 0) {
                if (row < N) {
                    __half2 hh = __floats2half2_rn(acc[mt][nt][0], acc[mt][nt][1]);
                    g_feat16[(size_t)row * 64 + (col >> 1)] = *(unsigned*)&hh;
                }
                if (row + 8 < N) {
                    __half2 hh = __floats2half2_rn(acc[mt][nt][2], acc[mt][nt][3]);
                    g_feat16[(size_t)(row + 8) * 64 + (col >> 1)] = *(unsigned*)&hh;
                }
            } else {
                if (row < N)
                    *(float2*)&res_out[(size_t)row * IN_DIM + col] =
                        make_float2(acc[mt][nt][0], acc[mt][nt][1]);
                if (row + 8 < N)
                    *(float2*)&res_out[(size_t)(row + 8) * IN_DIM + col] =
                        make_float2(acc[mt][nt][2], acc[mt][nt][3]);
            }
        }

    // ---------- fused el/er (feat blocks only; from fp32 accumulators) ----------
    if (o0 == 0) {
        float* se = (float*)smem_u;
        __syncthreads();
        int head = nw;
#pragma unroll
        for (int mt = 0; mt < 2; mt++)
#pragma unroll
            for (int half = 0; half < 2; half++) {
                float el = 0.f, er_ = 0.f;
#pragma unroll
                for (int nt = 0; nt < 4; nt++) {
                    int d = nt * 8 + t4 * 2;
                    float a0 = acc[mt][nt][half*2+0];
                    float a1 = acc[mt][nt][half*2+1];
                    el  += a0 * __ldg(&attn_l[head*32 + d]) + a1 * __ldg(&attn_l[head*32 + d + 1]);
                    er_ += a0 * __ldg(&attn_r[head*32 + d]) + a1 * __ldg(&attn_r[head*32 + d + 1]);
                }
                el  += __shfl_xor_sync(0xffffffffu, el, 1);
                el  += __shfl_xor_sync(0xffffffffu, el, 2);
                er_ += __shfl_xor_sync(0xffffffffu, er_, 1);
                er_ += __shfl_xor_sync(0xffffffffu, er_, 2);
                if (t4 == 0) {
                    int row = mbase + mt * 16 + half * 8 + g;
                    se[row * 8 + head]     = el;
                    se[row * 8 + 4 + head] = er_;
                }
            }
        __syncthreads();
        {
            int row = tid >> 2, hh = tid & 3;
            if (n0 + row < N) {
                g_el[(n0 + row) * NH + hh] = se[row * 8 + hh];
                g_er[(n0 + row) * NH + hh] = se[row * 8 + 4 + hh];
            }
        }
    }
}

// ---------------- edge softmax + aggregate + epilogue ----------------
__device__ __forceinline__ float4 leaky4(float4 e) {
    e.x = e.x > 0.f ? e.x : NEG_SLOPE * e.x;
    e.y = e.y > 0.f ? e.y : NEG_SLOPE * e.y;
    e.z = e.z > 0.f ? e.z : NEG_SLOPE * e.z;
    e.w = e.w > 0.f ? e.w : NEG_SLOPE * e.w;
    return e;
}

__global__ void k_attn(const float* __restrict__ bias, float* __restrict__ out, int N) {
    __shared__ int    s_src[8][32];
    __shared__ float4 s_a4[8][32];
    int t = threadIdx.x;
    int wid = t >> 5, lane = t & 31;
    int warp = blockIdx.x * 8 + wid;
    if (warp >= N) return;
    int rs = g_row[warp], re = g_row[warp + 1];
    float4 er4 = ((const float4*)g_er)[warp];

    // ---- pass 1a: plain max (no exp) ----
    float4 m = make_float4(-INFINITY, -INFINITY, -INFINITY, -INFINITY);
    for (int j = rs + lane; j < re; j += 32) {
        int s = g_src_s[j];
        float4 el4 = ((const float4*)g_el)[s];
        float4 e = leaky4(make_float4(el4.x + er4.x, el4.y + er4.y, el4.z + er4.z, el4.w + er4.w));
        m.x = fmaxf(m.x, e.x);
        m.y = fmaxf(m.y, e.y);
        m.z = fmaxf(m.z, e.z);
        m.w = fmaxf(m.w, e.w);
    }
    for (int off = 16; off >= 1; off >>= 1) {
        m.x = fmaxf(m.x, __shfl_xor_sync(0xffffffffu, m.x, off));
        m.y = fmaxf(m.y, __shfl_xor_sync(0xffffffffu, m.y, off));
        m.z = fmaxf(m.z, __shfl_xor_sync(0xffffffffu, m.z, off));
        m.w = fmaxf(m.w, __shfl_xor_sync(0xffffffffu, m.w, off));
    }

    // ---- pass 1b: sum of exp(e - m) ----
    float4 d = make_float4(0.f, 0.f, 0.f, 0.f);
    for (int j = rs + lane; j < re; j += 32) {
        int s = g_src_s[j];
        float4 el4 = ((const float4*)g_el)[s];
        float4 e = leaky4(make_float4(el4.x + er4.x, el4.y + er4.y, el4.z + er4.z, el4.w + er4.w));
        d.x += __expf(e.x - m.x);
        d.y += __expf(e.y - m.y);
        d.z += __expf(e.z - m.z);
        d.w += __expf(e.w - m.w);
    }
    for (int off = 16; off >= 1; off >>= 1) {
        d.x += __shfl_xor_sync(0xffffffffu, d.x, off);
        d.y += __shfl_xor_sync(0xffffffffu, d.y, off);
        d.z += __shfl_xor_sync(0xffffffffu, d.z, off);
        d.w += __shfl_xor_sync(0xffffffffu, d.w, off);
    }
    float4 inv4;
    inv4.x = 1.0f / fmaxf(d.x, 1e-9f);
    inv4.y = 1.0f / fmaxf(d.y, 1e-9f);
    inv4.z = 1.0f / fmaxf(d.z, 1e-9f);
    inv4.w = 1.0f / fmaxf(d.w, 1e-9f);

    int head = lane >> 3;
    float4 acc = make_float4(0.f, 0.f, 0.f, 0.f);

    // ---- pass 2: weights once per edge, staged via smem; fp16 feat gather ----
    for (int j0 = rs; j0 < re; j0 += 32) {
        int j = j0 + lane;
        int s = 0;
        float4 a4 = make_float4(0.f, 0.f, 0.f, 0.f);
        if (j < re) {
            s = g_src_s[j];
            float4 el4 = ((const float4*)g_el)[s];
            float4 e = leaky4(make_float4(el4.x + er4.x, el4.y + er4.y, el4.z + er4.z, el4.w + er4.w));
            a4.x = __expf(e.x - m.x) * inv4.x;
            a4.y = __expf(e.y - m.y) * inv4.y;
            a4.z = __expf(e.z - m.z) * inv4.z;
            a4.w = __expf(e.w - m.w) * inv4.w;
        }
        s_src[wid][lane] = s;
        s_a4[wid][lane]  = a4;
        __syncwarp();
        int cnt = min(32, re - j0);
        for (int i = 0; i < cnt; i++) {
            int sv = s_src[wid][i];
            float a = ((const float*)&s_a4[wid][i])[head];
            uint2 f = ((const uint2*)g_feat16)[(size_t)sv * 32 + lane];
            float2 f01 = __half22float2(*(__half2*)&f.x);
            float2 f23 = __half22float2(*(__half2*)&f.y);
            acc.x = fmaf(a, f01.x, acc.x);
            acc.y = fmaf(a, f01.y, acc.y);
            acc.z = fmaf(a, f23.x, acc.z);
            acc.w = fmaf(a, f23.y, acc.w);
        }
        __syncwarp();
    }

    float4 rr = ((const float4*)out)[(size_t)warp * 32 + lane];
    float4 b4 = ((const float4*)bias)[lane];
    float4 o;
    o.x = acc.x + rr.x + b4.x;
    o.y = acc.y + rr.y + b4.y;
    o.z = acc.z + rr.z + b4.z;
    o.w = acc.w + rr.w + b4.w;
    o.x = o.x > 0.f ? o.x : expm1f(o.x);
    o.y = o.y > 0.f ? o.y : expm1f(o.y);
    o.z = o.z > 0.f ? o.z : expm1f(o.z);
    o.w = o.w > 0.f ? o.w : expm1f(o.w);
    ((float4*)out)[(size_t)warp * 32 + lane] = o;
}

// ---------------- launch ----------------
extern "C" void kernel_launch(void* const* d_in, const int* in_sizes, int n_in,
                              void* d_out, int out_size) {
    const float* h      = (const float*)d_in[0];
    const float* tt     = (const float*)d_in[1];
    const int*   src    = (const int*)d_in[2];
    const int*   dst    = (const int*)d_in[3];
    const float* w_t    = (const float*)d_in[5];
    const float* b_t    = (const float*)d_in[6];
    const float* W_fc   = (const float*)d_in[7];
    const float* attn_l = (const float*)d_in[8];
    const float* attn_r = (const float*)d_in[9];
    const float* W_res  = (const float*)d_in[10];
    const float* bias   = (const float*)d_in[11];
    float* out = (float*)d_out;

    int N = in_sizes[0] / IN_DIM;
    int E = in_sizes[1];
    int NB = (N + 1023) / 1024;

    cudaFuncSetAttribute(k_gemm, cudaFuncAttributeMaxDynamicSharedMemorySize, SMEM_GEMM_BYTES);

    k_prep <<<128 + (N + 255) / 256, 256>>>(W_fc, W_res, N);
    k_count<<<(E + 255) / 256, 256>>>(dst, E);
    k_scan1<<<NB, 1024>>>(N);
    k_scan3<<<NB, 1024>>>(N, E);
    k_fill <<<(E + 255) / 256, 256>>>(src, dst, tt, E);
    k_agg  <<<(N * 32 + 255) / 256, 256>>>(h, w_t, b_t, N);
    dim3 gg((N + BM - 1) / BM, 2);
    k_gemm <<<gg, 512, SMEM_GEMM_BYTES>>>(out, attn_l, attn_r, N);
    k_attn <<<(N + 7) / 8, 256>>>(bias, out, N);
}

// round 16
// speedup vs baseline: 1.0339x; 1.0339x over previous
#include <cuda_runtime.h>
#include <cuda_bf16.h>
#include <cuda_fp16.h>
#include <math.h>

#define MAXN 50000
#define MAXE 800000
#define IN_DIM 128
#define TD 128
#define HT 256
#define NH 4
#define NEG_SLOPE 0.2f

// ---------------- device scratch (zero-initialized at load) ----------------
__device__ int   g_deg[MAXN];        // invariant: zero at kernel_launch entry
__device__ int   g_row[MAXN + 1];
__device__ int   g_cur[MAXN];
__device__ int   g_agg[64];
__device__ int   g_flag[64];         // epoch counters (monotonic across replays)
__device__ int   g_src_s[MAXE];
__device__ float g_t_s[MAXE];
__device__ float g_htime[(size_t)MAXN * HT];
__device__ unsigned g_feat16[(size_t)MAXN * 64];   // feat as packed half2
__device__ float g_el[MAXN * NH];
__device__ float g_er[MAXN * NH];
__device__ unsigned g_Whi[256 * 128];   // packed bf16x2 pairs along k
__device__ unsigned g_Wlo[256 * 128];

// ---------------- bf16 split helpers ----------------
__device__ __forceinline__ unsigned pk(__nv_bfloat16 a, __nv_bfloat16 b) {
    __nv_bfloat162 t = __halves2bfloat162(a, b);
    return *(unsigned*)&t;
}
__device__ __forceinline__ void bsplit2(float x0, float x1, unsigned &h, unsigned &l) {
    __nv_bfloat16 h0 = __float2bfloat16(x0);
    __nv_bfloat16 h1 = __float2bfloat16(x1);
    __nv_bfloat16 l0 = __float2bfloat16(x0 - __bfloat162float(h0));
    __nv_bfloat16 l1 = __float2bfloat16(x1 - __bfloat162float(h1));
    h = pk(h0, h1);
    l = pk(l0, l1);
}

// ------- W precompute (bf16 hi/lo) + degree count (fused; g_deg is zero on entry) --
__global__ void k_prep(const float* __restrict__ Wfc, const float* __restrict__ Wres,
                       const int* __restrict__ dst, int E) {
    int b = blockIdx.x;
    if (b < 128) {
        int idx = b * 256 + threadIdx.x;      // pair index 0..32767
        int row = idx >> 7, kp = idx & 127;
        const float* Wsrc = (row < 128) ? (Wfc + (size_t)row * 256)
                                        : (Wres + (size_t)(row - 128) * 256);
        float x0 = Wsrc[2 * kp], x1 = Wsrc[2 * kp + 1];
        unsigned h, l;
        bsplit2(x0, x1, h, l);
        g_Whi[idx] = h;
        g_Wlo[idx] = l;
    } else {
        int e = (b - 128) * 256 + threadIdx.x;
        if (e < E) atomicAdd(&g_deg[dst[e]], 1);
    }
}

// ---- fused exclusive scan (decoupled aggregate publish) + g_deg re-zero ----
// Grid: NB blocks of 1024; NB <= 64 and <= SM count -> all co-resident, spin-safe.
__global__ void k_scan(int N, int E) {
    __shared__ int s[1024];
    __shared__ int sepoch;
    __shared__ int sbase;
    int t = threadIdx.x, b = blockIdx.x;
    if (t == 0) sepoch = g_flag[b];       // own flag: written only by this block
    int i = b * 1024 + t;
    int v = (i < N) ? g_deg[i] : 0;
    s[t] = v;
    __syncthreads();
    for (int off = 1; off < 1024; off <<= 1) {
        int x = (t >= off) ? s[t - off] : 0;
        __syncthreads();
        s[t] += x;
        __syncthreads();
    }
    int epoch = sepoch;
    if (t == 1023) {
        g_agg[b] = s[1023];
        __threadfence();
        *(volatile int*)&g_flag[b] = epoch + 1;
    }
    // lanes of warp 0 gather predecessor aggregates (b <= 63 -> 2 per lane max)
    if (t < 32) {
        int sum = 0;
#pragma unroll
        for (int k = 0; k < 2; k++) {
            int j = t + k * 32;
            if (j < b) {
                while (*(volatile int*)&g_flag[j] <= epoch) { }
                sum += g_agg[j];
            }
        }
#pragma unroll
        for (int off = 16; off >= 1; off >>= 1)
            sum += __shfl_xor_sync(0xffffffffu, sum, off);
        if (t == 0) sbase = sum;
    }
    __syncthreads();
    if (i < N) {
        int ex = s[t] - v + sbase;
        g_row[i] = ex;
        g_cur[i] = ex;
        g_deg[i] = 0;                      // restore invariant for next replay
    }
    if (i == 0) g_row[N] = E;
}

__global__ void k_fill(const int* __restrict__ src, const int* __restrict__ dst,
                       const float* __restrict__ tt, int E) {
    int e = blockIdx.x * blockDim.x + threadIdx.x;
    if (e < E) {
        int slot = atomicAdd(&g_cur[dst[e]], 1);
        g_src_s[slot] = src[e];
        g_t_s[slot]   = tt[e];
    }
}

// ---------------- mailbox mean (warp per dst node) ----------------
__global__ void k_agg(const float* __restrict__ h,
                      const float* __restrict__ w_t,
                      const float* __restrict__ b_t, int N) {
    __shared__ float sw[TD], sb[TD];
    int t = threadIdx.x;
    for (int i = t; i < TD; i += blockDim.x) { sw[i] = w_t[i]; sb[i] = b_t[i]; }
    __syncthreads();
    int warp = (blockIdx.x * blockDim.x + t) >> 5;
    int lane = t & 31;
    if (warp >= N) return;
    int rs = g_row[warp], re = g_row[warp + 1];
    float w0 = sw[lane*4], w1 = sw[lane*4+1], w2 = sw[lane*4+2], w3 = sw[lane*4+3];
    float b0 = sb[lane*4], b1 = sb[lane*4+1], b2 = sb[lane*4+2], b3 = sb[lane*4+3];
    float4 ah = make_float4(0.f,0.f,0.f,0.f);
    float4 at = make_float4(0.f,0.f,0.f,0.f);
    const float4* h4 = (const float4*)h;
    for (int j = rs; j < re; j++) {
        int s = g_src_s[j];
        float4 hv = h4[(size_t)s * 32 + lane];
        ah.x += hv.x; ah.y += hv.y; ah.z += hv.z; ah.w += hv.w;
        float tv = g_t_s[j];
        at.x += __cosf(fmaf(tv, w0, b0));
        at.y += __cosf(fmaf(tv, w1, b1));
        at.z += __cosf(fmaf(tv, w2, b2));
        at.w += __cosf(fmaf(tv, w3, b3));
    }
    float inv = 1.0f / fmaxf((float)(re - rs), 1.0f);
    float4 o1 = make_float4(ah.x*inv, ah.y*inv, ah.z*inv, ah.w*inv);
    float4 o2 = make_float4(at.x*inv, at.y*inv, at.z*inv, at.w*inv);
    float4* ht4 = (float4*)g_htime;
    ht4[(size_t)warp * 64 + lane]      = o1;
    ht4[(size_t)warp * 64 + 32 + lane] = o2;
}

// ---------------- tensor-core GEMM (bf16x3, m16n8k16, double-buffered) ------------
#define BM 128
#define BN 128
#define BK 16
#define PADW 12
#define STAGEW (128 * PADW)
#define SMEM_GEMM_BYTES (4 * 2 * STAGEW * 4)   // 48 KB

#define MMA_BF16(C, A, B)                                                      \
  asm volatile("mma.sync.aligned.m16n8k16.row.col.f32.bf16.bf16.f32 "          \
    "{%0,%1,%2,%3}, {%4,%5,%6,%7}, {%8,%9}, {%0,%1,%2,%3};\n"                  \
    : "+f"(C[0]), "+f"(C[1]), "+f"(C[2]), "+f"(C[3])                           \
    : "r"(A[0]), "r"(A[1]), "r"(A[2]), "r"(A[3]), "r"(B[0]), "r"(B[1]))

__global__ __launch_bounds__(512)
void k_gemm(float* __restrict__ res_out,
            const float* __restrict__ attn_l, const float* __restrict__ attn_r, int N) {
    extern __shared__ unsigned smem_u[];
    unsigned* As_hi = smem_u;
    unsigned* As_lo = As_hi + 2 * STAGEW;
    unsigned* Bs_hi = As_lo + 2 * STAGEW;
    unsigned* Bs_lo = Bs_hi + 2 * STAGEW;
#define AH(st,m,w) As_hi[(st)*STAGEW + (m)*PADW + (w)]
#define AL(st,m,w) As_lo[(st)*STAGEW + (m)*PADW + (w)]
#define BH(st,n,w) Bs_hi[(st)*STAGEW + (n)*PADW + (w)]
#define BL(st,n,w) Bs_lo[(st)*STAGEW + (n)*PADW + (w)]

    int n0 = blockIdx.x * BM;
    int o0 = blockIdx.y * BN;
    int tid = threadIdx.x;
    int wid = tid >> 5, lane = tid & 31;
    int mw = wid >> 2, nw = wid & 3;
    int mbase = mw * 32, nbase = nw * 32;
    int g = lane >> 2, t4 = lane & 3;

    int a_r = tid >> 2, q = tid & 3;

    float4 pa = make_float4(0.f, 0.f, 0.f, 0.f);
    if (n0 + a_r < N)
        pa = *(const float4*)&g_htime[(size_t)(n0 + a_r) * HT + 4 * q];
    uint2 pbh = *(const uint2*)&g_Whi[(o0 + a_r) * 128 + 2 * q];
    uint2 pbl = *(const uint2*)&g_Wlo[(o0 + a_r) * 128 + 2 * q];

    {
        unsigned h0, l0, h1, l1;
        bsplit2(pa.x, pa.y, h0, l0);
        bsplit2(pa.z, pa.w, h1, l1);
        AH(0,a_r,2*q) = h0;  AH(0,a_r,2*q+1) = h1;
        AL(0,a_r,2*q) = l0;  AL(0,a_r,2*q+1) = l1;
        BH(0,a_r,2*q) = pbh.x; BH(0,a_r,2*q+1) = pbh.y;
        BL(0,a_r,2*q) = pbl.x; BL(0,a_r,2*q+1) = pbl.y;
    }
    __syncthreads();

    float acc[2][4][4];
#pragma unroll
    for (int i = 0; i < 2; i++)
#pragma unroll
        for (int j = 0; j < 4; j++)
#pragma unroll
            for (int k = 0; k < 4; k++) acc[i][j][k] = 0.f;

    int st = 0;
    for (int k0 = 0; k0 < HT; k0 += BK, st ^= 1) {
        int nk = k0 + BK;
        if (nk < HT) {
            pa = make_float4(0.f, 0.f, 0.f, 0.f);
            if (n0 + a_r < N)
                pa = *(const float4*)&g_htime[(size_t)(n0 + a_r) * HT + nk + 4 * q];
            pbh = *(const uint2*)&g_Whi[(o0 + a_r) * 128 + (nk >> 1) + 2 * q];
            pbl = *(const uint2*)&g_Wlo[(o0 + a_r) * 128 + (nk >> 1) + 2 * q];
        }
        unsigned ah[2][4], al[2][4], bh[4][2], bl[4][2];
#pragma unroll
        for (int mt = 0; mt < 2; mt++) {
            int ar = mbase + mt * 16 + g;
            ah[mt][0] = AH(st,ar,t4);    ah[mt][1] = AH(st,ar+8,t4);
            ah[mt][2] = AH(st,ar,t4+4);  ah[mt][3] = AH(st,ar+8,t4+4);
            al[mt][0] = AL(st,ar,t4);    al[mt][1] = AL(st,ar+8,t4);
            al[mt][2] = AL(st,ar,t4+4);  al[mt][3] = AL(st,ar+8,t4+4);
        }
#pragma unroll
        for (int nt = 0; nt < 4; nt++) {
            int bc = nbase + nt * 8 + g;
            bh[nt][0] = BH(st,bc,t4);    bh[nt][1] = BH(st,bc,t4+4);
            bl[nt][0] = BL(st,bc,t4);    bl[nt][1] = BL(st,bc,t4+4);
        }
#pragma unroll
        for (int mt = 0; mt < 2; mt++)
#pragma unroll
            for (int nt = 0; nt < 4; nt++) {
                MMA_BF16(acc[mt][nt], ah[mt], bh[nt]);
                MMA_BF16(acc[mt][nt], al[mt], bh[nt]);
                MMA_BF16(acc[mt][nt], ah[mt], bl[nt]);
            }
        if (nk < HT) {
            int ns = st ^ 1;
            unsigned h0, l0, h1, l1;
            bsplit2(pa.x, pa.y, h0, l0);
            bsplit2(pa.z, pa.w, h1, l1);
            AH(ns,a_r,2*q) = h0;  AH(ns,a_r,2*q+1) = h1;
            AL(ns,a_r,2*q) = l0;  AL(ns,a_r,2*q+1) = l1;
            BH(ns,a_r,2*q) = pbh.x; BH(ns,a_r,2*q+1) = pbh.y;
            BL(ns,a_r,2*q) = pbl.x; BL(ns,a_r,2*q+1) = pbl.y;
        }
        __syncthreads();
    }

    // ---------- store C: feat -> packed fp16, res -> fp32 ----------
#pragma unroll
    for (int mt = 0; mt < 2; mt++)
#pragma unroll
        for (int nt = 0; nt < 4; nt++) {
            int row = n0 + mbase + mt * 16 + g;
            int col = nbase + nt * 8 + t4 * 2;
            if (o0 == 0) {
                if (row < N) {
                    __half2 hh = __floats2half2_rn(acc[mt][nt][0], acc[mt][nt][1]);
                    g_feat16[(size_t)row * 64 + (col >> 1)] = *(unsigned*)&hh;
                }
                if (row + 8 < N) {
                    __half2 hh = __floats2half2_rn(acc[mt][nt][2], acc[mt][nt][3]);
                    g_feat16[(size_t)(row + 8) * 64 + (col >> 1)] = *(unsigned*)&hh;
                }
            } else {
                if (row < N)
                    *(float2*)&res_out[(size_t)row * IN_DIM + col] =
                        make_float2(acc[mt][nt][0], acc[mt][nt][1]);
                if (row + 8 < N)
                    *(float2*)&res_out[(size_t)(row + 8) * IN_DIM + col] =
                        make_float2(acc[mt][nt][2], acc[mt][nt][3]);
            }
        }

    // ---------- fused el/er (feat blocks only; from fp32 accumulators) ----------
    if (o0 == 0) {
        float* se = (float*)smem_u;
        __syncthreads();
        int head = nw;
#pragma unroll
        for (int mt = 0; mt < 2; mt++)
#pragma unroll
            for (int half = 0; half < 2; half++) {
                float el = 0.f, er_ = 0.f;
#pragma unroll
                for (int nt = 0; nt < 4; nt++) {
                    int d = nt * 8 + t4 * 2;
                    float a0 = acc[mt][nt][half*2+0];
                    float a1 = acc[mt][nt][half*2+1];
                    el  += a0 * __ldg(&attn_l[head*32 + d]) + a1 * __ldg(&attn_l[head*32 + d + 1]);
                    er_ += a0 * __ldg(&attn_r[head*32 + d]) + a1 * __ldg(&attn_r[head*32 + d + 1]);
                }
                el  += __shfl_xor_sync(0xffffffffu, el, 1);
                el  += __shfl_xor_sync(0xffffffffu, el, 2);
                er_ += __shfl_xor_sync(0xffffffffu, er_, 1);
                er_ += __shfl_xor_sync(0xffffffffu, er_, 2);
                if (t4 == 0) {
                    int row = mbase + mt * 16 + half * 8 + g;
                    se[row * 8 + head]     = el;
                    se[row * 8 + 4 + head] = er_;
                }
            }
        __syncthreads();
        {
            int row = tid >> 2, hh = tid & 3;
            if (n0 + row < N) {
                g_el[(n0 + row) * NH + hh] = se[row * 8 + hh];
                g_er[(n0 + row) * NH + hh] = se[row * 8 + 4 + hh];
            }
        }
    }
}

// ---------------- edge softmax + aggregate + epilogue ----------------
__device__ __forceinline__ float4 leaky4(float4 e) {
    e.x = e.x > 0.f ? e.x : NEG_SLOPE * e.x;
    e.y = e.y > 0.f ? e.y : NEG_SLOPE * e.y;
    e.z = e.z > 0.f ? e.z : NEG_SLOPE * e.z;
    e.w = e.w > 0.f ? e.w : NEG_SLOPE * e.w;
    return e;
}

__global__ void k_attn(const float* __restrict__ bias, float* __restrict__ out, int N) {
    __shared__ int    s_src[8][32];
    __shared__ float4 s_a4[8][32];
    int t = threadIdx.x;
    int wid = t >> 5, lane = t & 31;
    int warp = blockIdx.x * 8 + wid;
    if (warp >= N) return;
    int rs = g_row[warp], re = g_row[warp + 1];
    float4 er4 = ((const float4*)g_er)[warp];

    // ---- pass 1a: plain max (no exp) ----
    float4 m = make_float4(-INFINITY, -INFINITY, -INFINITY, -INFINITY);
    for (int j = rs + lane; j < re; j += 32) {
        int s = g_src_s[j];
        float4 el4 = ((const float4*)g_el)[s];
        float4 e = leaky4(make_float4(el4.x + er4.x, el4.y + er4.y, el4.z + er4.z, el4.w + er4.w));
        m.x = fmaxf(m.x, e.x);
        m.y = fmaxf(m.y, e.y);
        m.z = fmaxf(m.z, e.z);
        m.w = fmaxf(m.w, e.w);
    }
    for (int off = 16; off >= 1; off >>= 1) {
        m.x = fmaxf(m.x, __shfl_xor_sync(0xffffffffu, m.x, off));
        m.y = fmaxf(m.y, __shfl_xor_sync(0xffffffffu, m.y, off));
        m.z = fmaxf(m.z, __shfl_xor_sync(0xffffffffu, m.z, off));
        m.w = fmaxf(m.w, __shfl_xor_sync(0xffffffffu, m.w, off));
    }

    // ---- pass 1b: sum of exp(e - m) ----
    float4 d = make_float4(0.f, 0.f, 0.f, 0.f);
    for (int j = rs + lane; j < re; j += 32) {
        int s = g_src_s[j];
        float4 el4 = ((const float4*)g_el)[s];
        float4 e = leaky4(make_float4(el4.x + er4.x, el4.y + er4.y, el4.z + er4.z, el4.w + er4.w));
        d.x += __expf(e.x - m.x);
        d.y += __expf(e.y - m.y);
        d.z += __expf(e.z - m.z);
        d.w += __expf(e.w - m.w);
    }
    for (int off = 16; off >= 1; off >>= 1) {
        d.x += __shfl_xor_sync(0xffffffffu, d.x, off);
        d.y += __shfl_xor_sync(0xffffffffu, d.y, off);
        d.z += __shfl_xor_sync(0xffffffffu, d.z, off);
        d.w += __shfl_xor_sync(0xffffffffu, d.w, off);
    }
    float4 inv4;
    inv4.x = 1.0f / fmaxf(d.x, 1e-9f);
    inv4.y = 1.0f / fmaxf(d.y, 1e-9f);
    inv4.z = 1.0f / fmaxf(d.z, 1e-9f);
    inv4.w = 1.0f / fmaxf(d.w, 1e-9f);

    int head = lane >> 3;
    float4 acc = make_float4(0.f, 0.f, 0.f, 0.f);

    // ---- pass 2: weights once per edge, staged via smem; fp16 feat gather ----
    for (int j0 = rs; j0 < re; j0 += 32) {
        int j = j0 + lane;
        int s = 0;
        float4 a4 = make_float4(0.f, 0.f, 0.f, 0.f);
        if (j < re) {
            s = g_src_s[j];
            float4 el4 = ((const float4*)g_el)[s];
            float4 e = leaky4(make_float4(el4.x + er4.x, el4.y + er4.y, el4.z + er4.z, el4.w + er4.w));
            a4.x = __expf(e.x - m.x) * inv4.x;
            a4.y = __expf(e.y - m.y) * inv4.y;
            a4.z = __expf(e.z - m.z) * inv4.z;
            a4.w = __expf(e.w - m.w) * inv4.w;
        }
        s_src[wid][lane] = s;
        s_a4[wid][lane]  = a4;
        __syncwarp();
        int cnt = min(32, re - j0);
        for (int i = 0; i < cnt; i++) {
            int sv = s_src[wid][i];
            float a = ((const float*)&s_a4[wid][i])[head];
            uint2 f = ((const uint2*)g_feat16)[(size_t)sv * 32 + lane];
            float2 f01 = __half22float2(*(__half2*)&f.x);
            float2 f23 = __half22float2(*(__half2*)&f.y);
            acc.x = fmaf(a, f01.x, acc.x);
            acc.y = fmaf(a, f01.y, acc.y);
            acc.z = fmaf(a, f23.x, acc.z);
            acc.w = fmaf(a, f23.y, acc.w);
        }
        __syncwarp();
    }

    float4 rr = ((const float4*)out)[(size_t)warp * 32 + lane];
    float4 b4 = ((const float4*)bias)[lane];
    float4 o;
    o.x = acc.x + rr.x + b4.x;
    o.y = acc.y + rr.y + b4.y;
    o.z = acc.z + rr.z + b4.z;
    o.w = acc.w + rr.w + b4.w;
    o.x = o.x > 0.f ? o.x : expm1f(o.x);
    o.y = o.y > 0.f ? o.y : expm1f(o.y);
    o.z = o.z > 0.f ? o.z : expm1f(o.z);
    o.w = o.w > 0.f ? o.w : expm1f(o.w);
    ((float4*)out)[(size_t)warp * 32 + lane] = o;
}

// ---------------- launch ----------------
extern "C" void kernel_launch(void* const* d_in, const int* in_sizes, int n_in,
                              void* d_out, int out_size) {
    const float* h      = (const float*)d_in[0];
    const float* tt     = (const float*)d_in[1];
    const int*   src    = (const int*)d_in[2];
    const int*   dst    = (const int*)d_in[3];
    const float* w_t    = (const float*)d_in[5];
    const float* b_t    = (const float*)d_in[6];
    const float* W_fc   = (const float*)d_in[7];
    const float* attn_l = (const float*)d_in[8];
    const float* attn_r = (const float*)d_in[9];
    const float* W_res  = (const float*)d_in[10];
    const float* bias   = (const float*)d_in[11];
    float* out = (float*)d_out;

    int N = in_sizes[0] / IN_DIM;
    int E = in_sizes[1];
    int NB = (N + 1023) / 1024;

    cudaFuncSetAttribute(k_gemm, cudaFuncAttributeMaxDynamicSharedMemorySize, SMEM_GEMM_BYTES);

    k_prep <<<128 + (E + 255) / 256, 256>>>(W_fc, W_res, dst, E);
    k_scan <<<NB, 1024>>>(N, E);
    k_fill <<<(E + 255) / 256, 256>>>(src, dst, tt, E);
    k_agg  <<<(N * 32 + 255) / 256, 256>>>(h, w_t, b_t, N);
    dim3 gg((N + BM - 1) / BM, 2);
    k_gemm <<<gg, 512, SMEM_GEMM_BYTES>>>(out, attn_l, attn_r, N);
    k_attn <<<(N + 7) / 8, 256>>>(bias, out, N);
}